// round 5
// baseline (speedup 1.0000x reference)
#include <cuda_runtime.h>
#include <float.h>

#define C_DIM 512
#define H_DIM 50
#define W_DIM 75
#define HW_DIM (H_DIM * W_DIM)
#define NROI 512
#define PRE 14
#define PADC 132   // stage row stride in floats (33 float4)

// channels-last scratch copy of the feature map: [H*W, C]
__device__ __align__(16) float g_featT[HW_DIM * C_DIM];

// -------------------------------------------------------------------------
// Tiled transpose: bottom [C, H*W] -> g_featT [H*W, C]
// -------------------------------------------------------------------------
__global__ void transpose_kernel(const float* __restrict__ in) {
    __shared__ float tile[32][33];
    int hw0 = blockIdx.x * 32;
    int c0  = blockIdx.y * 32;
    int tx = threadIdx.x, ty = threadIdx.y;

    #pragma unroll
    for (int j = 0; j < 32; j += 8) {
        int hw = hw0 + tx;
        int c  = c0 + ty + j;
        if (hw < HW_DIM) tile[ty + j][tx] = in[c * HW_DIM + hw];
    }
    __syncthreads();
    #pragma unroll
    for (int j = 0; j < 32; j += 8) {
        int hw = hw0 + ty + j;
        int c  = c0 + tx;
        if (hw < HW_DIM) g_featT[hw * C_DIM + c] = tile[tx][ty + j];
    }
}

// -------------------------------------------------------------------------
// Main kernel: grid (512 rois, 4 channel-quarters, 2 pixel-halves),
// 128 threads (4 warps). Lane owns 4 consecutive channels (float4); a warp
// covers the 128-channel quarter; the 4 warps split this block's ~24/25
// output pixels round-robin. R2-style inner loop: 16 independent LDG.128.
// -------------------------------------------------------------------------
__global__ __launch_bounds__(128, 7) void roi_pool_kernel(
    const float* __restrict__ rois, float* __restrict__ out) {

    // Packed corner tables: (.x = off0 bits, .y = off1 bits, .z = w0, .w = w1),
    // offsets in float4 units.
    __shared__ float4 tabx[PRE], taby[PRE];
    __shared__ __align__(16) float stage[25 * PADC];

    const int n  = blockIdx.x;
    const int t  = threadIdx.x;
    const int z  = blockIdx.z;
    const int p0 = z * 24;            // pixel window start
    const int np = z ? 25 : 24;       // pixel window size

    // ---- per-ROI corner tables (threads 0..27) ----
    if (t < 2 * PRE) {
        const int axis = (t >= PRE);          // 0 = x, 1 = y
        const int i = axis ? (t - PRE) : t;
        const float lo = rois[n * 5 + (axis ? 2 : 1)] * (1.0f / 16.0f);
        const float hi = rois[n * 5 + (axis ? 4 : 3)] * (1.0f / 16.0f);
        const int D = axis ? H_DIM : W_DIM;

        // replicate reference math exactly
        float s  = (hi - lo) / (float)(D - 1);
        float tt = (lo + hi - (float)(D - 1)) / (float)(D - 1);
        float base = -1.0f + (float)i * (2.0f / 13.0f);
        float g  = s * base + tt;
        float xc = (g + 1.0f) * 0.5f * (float)(D - 1);

        float f0 = floorf(xc);
        int   i0 = (int)f0;
        float w1 = xc - f0;
        float w0 = 1.0f - w1;
        float v0 = (i0 >= 0 && i0 <= D - 1) ? 1.0f : 0.0f;
        float v1 = (i0 + 1 >= 0 && i0 + 1 <= D - 1) ? 1.0f : 0.0f;
        int c0 = min(max(i0, 0), D - 1);
        int c1 = min(max(i0 + 1, 0), D - 1);

        int mul = axis ? (W_DIM * (C_DIM / 4)) : (C_DIM / 4);
        float4 e;
        e.x = __int_as_float(c0 * mul);
        e.y = __int_as_float(c1 * mul);
        e.z = w0 * v0;
        e.w = w1 * v1;
        if (axis) taby[i] = e; else tabx[i] = e;
    }
    __syncthreads();

    const int w    = t >> 5;
    const int lane = t & 31;
    const float4* __restrict__ fb =
        (const float4*)g_featT + blockIdx.y * 32 + lane;
    float4* stage4 = (float4*)stage;

    for (int p = p0 + w; p < p0 + np; p += 4) {
        const int py = p / 7;
        const int px = p - py * 7;

        const float4 tx0 = tabx[2 * px];
        const float4 tx1 = tabx[2 * px + 1];
        const float4 ty0 = taby[2 * py];
        const float4 ty1 = taby[2 * py + 1];

        float4 m = make_float4(-FLT_MAX, -FLT_MAX, -FLT_MAX, -FLT_MAX);

        #pragma unroll
        for (int dy = 0; dy < 2; dy++) {
            const float4 ty = dy ? ty1 : ty0;
            const int oy0 = __float_as_int(ty.x);
            const int oy1 = __float_as_int(ty.y);
            const float wy0 = ty.z, wy1 = ty.w;
            #pragma unroll
            for (int dx = 0; dx < 2; dx++) {
                const float4 tx = dx ? tx1 : tx0;
                const int ox0 = __float_as_int(tx.x);
                const int ox1 = __float_as_int(tx.y);
                const float wx0 = tx.z, wx1 = tx.w;

                float4 f00 = fb[oy0 + ox0];
                float4 f01 = fb[oy0 + ox1];
                float4 f10 = fb[oy1 + ox0];
                float4 f11 = fb[oy1 + ox1];

                float4 v;
                v.x = (f00.x * wx0 + f01.x * wx1) * wy0 + (f10.x * wx0 + f11.x * wx1) * wy1;
                v.y = (f00.y * wx0 + f01.y * wx1) * wy0 + (f10.y * wx0 + f11.y * wx1) * wy1;
                v.z = (f00.z * wx0 + f01.z * wx1) * wy0 + (f10.z * wx0 + f11.z * wx1) * wy1;
                v.w = (f00.w * wx0 + f01.w * wx1) * wy0 + (f10.w * wx0 + f11.w * wx1) * wy1;
                m.x = fmaxf(m.x, v.x);
                m.y = fmaxf(m.y, v.y);
                m.z = fmaxf(m.z, v.z);
                m.w = fmaxf(m.w, v.w);
            }
        }
        // pixel-major stage: float4 store, conflict-free
        stage4[(p - p0) * (PADC / 4) + lane] = m;
    }
    __syncthreads();

    // ---- coalesced writeback: 128*np floats, idx = t + k*128 walked
    // incrementally over (c, pp) with pp fastest (pp in [0, np)).
    float* __restrict__ ob = out + (size_t)n * (C_DIM * 49)
                                 + (size_t)blockIdx.y * (128 * 49) + p0;
    const int q = 128 / np;   // 5 for both np values
    const int r = 128 - q * np;
    int c  = t / np;
    int pp = t - c * np;
    for (int k = 0; k < np; k++) {
        ob[c * 49 + pp] = stage[pp * PADC + c];
        pp += r; c += q;
        if (pp >= np) { pp -= np; c += 1; }
    }
}

// -------------------------------------------------------------------------
extern "C" void kernel_launch(void* const* d_in, const int* in_sizes, int n_in,
                              void* d_out, int out_size) {
    const float* bottom = (const float*)d_in[0];
    const float* rois   = (const float*)d_in[1];
    if (n_in >= 2 && in_sizes[0] == NROI * 5) {
        bottom = (const float*)d_in[1];
        rois   = (const float*)d_in[0];
    }
    float* out = (float*)d_out;

    dim3 tgrid((HW_DIM + 31) / 32, C_DIM / 32);
    transpose_kernel<<<tgrid, dim3(32, 8)>>>(bottom);

    dim3 rgrid(NROI, 4, 2);
    roi_pool_kernel<<<rgrid, 128>>>(rois, out);
}

// round 6
// speedup vs baseline: 1.1611x; 1.1611x over previous
#include <cuda_runtime.h>
#include <cuda_fp16.h>
#include <float.h>

#define C_DIM 512
#define H_DIM 50
#define W_DIM 75
#define HW_DIM (H_DIM * W_DIM)
#define NROI 512
#define PRE 14
#define PADC 132   // stage row stride in floats (33 float4)

// channels-last fp16 copy of the feature map: [H*W, C]
__device__ __align__(16) __half g_featT[HW_DIM * C_DIM];

// -------------------------------------------------------------------------
// Tiled transpose + fp16 quantize: bottom [C, H*W] -> g_featT [H*W, C]
// -------------------------------------------------------------------------
__global__ void transpose_kernel(const float* __restrict__ in) {
    __shared__ float tile[32][33];
    int hw0 = blockIdx.x * 32;
    int c0  = blockIdx.y * 32;
    int tx = threadIdx.x, ty = threadIdx.y;

    #pragma unroll
    for (int j = 0; j < 32; j += 8) {
        int hw = hw0 + tx;
        int c  = c0 + ty + j;
        if (hw < HW_DIM) tile[ty + j][tx] = in[c * HW_DIM + hw];
    }
    __syncthreads();
    #pragma unroll
    for (int j = 0; j < 32; j += 8) {
        int hw = hw0 + ty + j;
        int c  = c0 + tx;
        if (hw < HW_DIM)
            g_featT[hw * C_DIM + c] = __float2half_rn(tile[tx][ty + j]);
    }
}

// 4 fp16 channels -> float4 (fp32 math everywhere downstream)
__device__ __forceinline__ float4 h4_to_f4(uint2 r) {
    float2 f0 = __half22float2(*reinterpret_cast<__half2*>(&r.x));
    float2 f1 = __half22float2(*reinterpret_cast<__half2*>(&r.y));
    return make_float4(f0.x, f0.y, f1.x, f1.y);
}

// -------------------------------------------------------------------------
// Main kernel: grid (512 rois, 4 channel-quarters), 128 threads (4 warps).
// Lane owns 4 consecutive channels (8B fp16 load); warp covers the
// 128-channel quarter; the 4 warps split the 49 output pixels round-robin.
// -------------------------------------------------------------------------
__global__ __launch_bounds__(128, 7) void roi_pool_kernel(
    const float* __restrict__ rois, float* __restrict__ out) {

    // Packed corner tables: (.x = off0 bits, .y = off1 bits, .z = w0, .w = w1),
    // offsets in 4-channel (uint2) units.
    __shared__ float4 tabx[PRE], taby[PRE];
    __shared__ __align__(16) float stage[49 * PADC];

    const int n = blockIdx.x;
    const int t = threadIdx.x;

    // ---- per-ROI corner tables (threads 0..27) ----
    if (t < 2 * PRE) {
        const int axis = (t >= PRE);          // 0 = x, 1 = y
        const int i = axis ? (t - PRE) : t;
        const float lo = rois[n * 5 + (axis ? 2 : 1)] * (1.0f / 16.0f);
        const float hi = rois[n * 5 + (axis ? 4 : 3)] * (1.0f / 16.0f);
        const int D = axis ? H_DIM : W_DIM;

        // replicate reference math exactly
        float s  = (hi - lo) / (float)(D - 1);
        float tt = (lo + hi - (float)(D - 1)) / (float)(D - 1);
        float base = -1.0f + (float)i * (2.0f / 13.0f);
        float g  = s * base + tt;
        float xc = (g + 1.0f) * 0.5f * (float)(D - 1);

        float f0 = floorf(xc);
        int   i0 = (int)f0;
        float w1 = xc - f0;
        float w0 = 1.0f - w1;
        float v0 = (i0 >= 0 && i0 <= D - 1) ? 1.0f : 0.0f;
        float v1 = (i0 + 1 >= 0 && i0 + 1 <= D - 1) ? 1.0f : 0.0f;
        int c0 = min(max(i0, 0), D - 1);
        int c1 = min(max(i0 + 1, 0), D - 1);

        int mul = axis ? (W_DIM * (C_DIM / 4)) : (C_DIM / 4);
        float4 e;
        e.x = __int_as_float(c0 * mul);
        e.y = __int_as_float(c1 * mul);
        e.z = w0 * v0;
        e.w = w1 * v1;
        if (axis) taby[i] = e; else tabx[i] = e;
    }
    __syncthreads();

    const int w    = t >> 5;
    const int lane = t & 31;
    const uint2* __restrict__ fb =
        (const uint2*)g_featT + blockIdx.y * 32 + lane;
    float4* stage4 = (float4*)stage;

    for (int p = w; p < 49; p += 4) {
        const int py = p / 7;
        const int px = p - py * 7;

        const float4 tx0 = tabx[2 * px];
        const float4 tx1 = tabx[2 * px + 1];
        const float4 ty0 = taby[2 * py];
        const float4 ty1 = taby[2 * py + 1];

        float4 m = make_float4(-FLT_MAX, -FLT_MAX, -FLT_MAX, -FLT_MAX);

        #pragma unroll
        for (int dy = 0; dy < 2; dy++) {
            const float4 ty = dy ? ty1 : ty0;
            const int oy0 = __float_as_int(ty.x);
            const int oy1 = __float_as_int(ty.y);
            const float wy0 = ty.z, wy1 = ty.w;
            #pragma unroll
            for (int dx = 0; dx < 2; dx++) {
                const float4 tx = dx ? tx1 : tx0;
                const int ox0 = __float_as_int(tx.x);
                const int ox1 = __float_as_int(tx.y);
                const float wx0 = tx.z, wx1 = tx.w;

                uint2 r00 = fb[oy0 + ox0];
                uint2 r01 = fb[oy0 + ox1];
                uint2 r10 = fb[oy1 + ox0];
                uint2 r11 = fb[oy1 + ox1];

                float4 f00 = h4_to_f4(r00);
                float4 f01 = h4_to_f4(r01);
                float4 f10 = h4_to_f4(r10);
                float4 f11 = h4_to_f4(r11);

                float4 v;
                v.x = (f00.x * wx0 + f01.x * wx1) * wy0 + (f10.x * wx0 + f11.x * wx1) * wy1;
                v.y = (f00.y * wx0 + f01.y * wx1) * wy0 + (f10.y * wx0 + f11.y * wx1) * wy1;
                v.z = (f00.z * wx0 + f01.z * wx1) * wy0 + (f10.z * wx0 + f11.z * wx1) * wy1;
                v.w = (f00.w * wx0 + f01.w * wx1) * wy0 + (f10.w * wx0 + f11.w * wx1) * wy1;
                m.x = fmaxf(m.x, v.x);
                m.y = fmaxf(m.y, v.y);
                m.z = fmaxf(m.z, v.z);
                m.w = fmaxf(m.w, v.w);
            }
        }
        // pixel-major stage: float4 store, conflict-free
        stage4[p * (PADC / 4) + lane] = m;
    }
    __syncthreads();

    // ---- coalesced writeback: 6272 floats, idx = t + k*128 walked incrementally
    float* __restrict__ ob = out + (size_t)n * (C_DIM * 49)
                                 + (size_t)blockIdx.y * (128 * 49);
    int c = t / 49;
    int p = t - c * 49;
    #pragma unroll 7
    for (int k = 0; k < 49; k++) {
        ob[t + k * 128] = stage[p * PADC + c];
        p += 30; c += 2;              // advance by 128 = 2*49 + 30
        if (p >= 49) { p -= 49; c += 1; }
    }
}

// -------------------------------------------------------------------------
extern "C" void kernel_launch(void* const* d_in, const int* in_sizes, int n_in,
                              void* d_out, int out_size) {
    const float* bottom = (const float*)d_in[0];
    const float* rois   = (const float*)d_in[1];
    if (n_in >= 2 && in_sizes[0] == NROI * 5) {
        bottom = (const float*)d_in[1];
        rois   = (const float*)d_in[0];
    }
    float* out = (float*)d_out;

    dim3 tgrid((HW_DIM + 31) / 32, C_DIM / 32);
    transpose_kernel<<<tgrid, dim3(32, 8)>>>(bottom);

    dim3 rgrid(NROI, 4);
    roi_pool_kernel<<<rgrid, 128>>>(rois, out);
}

// round 7
// speedup vs baseline: 1.4191x; 1.2221x over previous
#include <cuda_runtime.h>
#include <cuda_fp16.h>
#include <float.h>

#define C_DIM 512
#define H_DIM 50
#define W_DIM 75
#define HW_DIM (H_DIM * W_DIM)
#define NROI 512
#define PRE 14
#define PADC 132   // stage row stride in floats (33 float4)

// channels-last fp16 copy of the feature map: [H*W, C]
__device__ __align__(16) __half g_featT[HW_DIM * C_DIM];

// -------------------------------------------------------------------------
// Tiled transpose + fp16 quantize: bottom [C, H*W] -> g_featT [H*W, C]
// -------------------------------------------------------------------------
__global__ void transpose_kernel(const float* __restrict__ in) {
    __shared__ float tile[32][33];
    int hw0 = blockIdx.x * 32;
    int c0  = blockIdx.y * 32;
    int tx = threadIdx.x, ty = threadIdx.y;

    #pragma unroll
    for (int j = 0; j < 32; j += 8) {
        int hw = hw0 + tx;
        int c  = c0 + ty + j;
        if (hw < HW_DIM) tile[ty + j][tx] = in[c * HW_DIM + hw];
    }
    __syncthreads();
    #pragma unroll
    for (int j = 0; j < 32; j += 8) {
        int hw = hw0 + ty + j;
        int c  = c0 + tx;
        if (hw < HW_DIM)
            g_featT[hw * C_DIM + c] = __float2half_rn(tile[tx][ty + j]);
    }
}

// -------------------------------------------------------------------------
// Main kernel: grid (512 rois, 4 channel-quarters), 128 threads (4 warps).
// Lane owns 4 consecutive channels (8B fp16 load = 2 half2); warp covers the
// 128-channel quarter; the 4 warps split the 49 output pixels round-robin.
// Bilinear sample = corner-sum in half2: v = f00*w00+f01*w01+f10*w10+f11*w11
// with corner weights computed in fp32 and broadcast-packed to half2.
// -------------------------------------------------------------------------
__global__ __launch_bounds__(128, 8) void roi_pool_kernel(
    const float* __restrict__ rois, float* __restrict__ out) {

    // Packed corner tables: (.x = off0 bits, .y = off1 bits, .z = w0, .w = w1),
    // offsets in 4-channel (uint2) units.
    __shared__ float4 tabx[PRE], taby[PRE];
    __shared__ __align__(16) float stage[49 * PADC];

    const int n = blockIdx.x;
    const int t = threadIdx.x;

    // ---- per-ROI corner tables (threads 0..27) ----
    if (t < 2 * PRE) {
        const int axis = (t >= PRE);          // 0 = x, 1 = y
        const int i = axis ? (t - PRE) : t;
        const float lo = rois[n * 5 + (axis ? 2 : 1)] * (1.0f / 16.0f);
        const float hi = rois[n * 5 + (axis ? 4 : 3)] * (1.0f / 16.0f);
        const int D = axis ? H_DIM : W_DIM;

        // replicate reference math exactly
        float s  = (hi - lo) / (float)(D - 1);
        float tt = (lo + hi - (float)(D - 1)) / (float)(D - 1);
        float base = -1.0f + (float)i * (2.0f / 13.0f);
        float g  = s * base + tt;
        float xc = (g + 1.0f) * 0.5f * (float)(D - 1);

        float f0 = floorf(xc);
        int   i0 = (int)f0;
        float w1 = xc - f0;
        float w0 = 1.0f - w1;
        float v0 = (i0 >= 0 && i0 <= D - 1) ? 1.0f : 0.0f;
        float v1 = (i0 + 1 >= 0 && i0 + 1 <= D - 1) ? 1.0f : 0.0f;
        int c0 = min(max(i0, 0), D - 1);
        int c1 = min(max(i0 + 1, 0), D - 1);

        int mul = axis ? (W_DIM * (C_DIM / 4)) : (C_DIM / 4);
        float4 e;
        e.x = __int_as_float(c0 * mul);
        e.y = __int_as_float(c1 * mul);
        e.z = w0 * v0;
        e.w = w1 * v1;
        if (axis) taby[i] = e; else tabx[i] = e;
    }
    __syncthreads();

    const int w    = t >> 5;
    const int lane = t & 31;
    const uint2* __restrict__ fb =
        (const uint2*)g_featT + blockIdx.y * 32 + lane;
    float4* stage4 = (float4*)stage;

    const __half2 HMIN = __float2half2_rn(-60000.0f);

    for (int p = w; p < 49; p += 4) {
        const int py = p / 7;
        const int px = p - py * 7;

        const float4 tx0 = tabx[2 * px];
        const float4 tx1 = tabx[2 * px + 1];
        const float4 ty0 = taby[2 * py];
        const float4 ty1 = taby[2 * py + 1];

        __half2 m01 = HMIN;   // channels 0,1
        __half2 m23 = HMIN;   // channels 2,3

        #pragma unroll
        for (int dy = 0; dy < 2; dy++) {
            const float4 ty = dy ? ty1 : ty0;
            const int oy0 = __float_as_int(ty.x);
            const int oy1 = __float_as_int(ty.y);
            const float wy0 = ty.z, wy1 = ty.w;
            #pragma unroll
            for (int dx = 0; dx < 2; dx++) {
                const float4 tx = dx ? tx1 : tx0;
                const int ox0 = __float_as_int(tx.x);
                const int ox1 = __float_as_int(tx.y);

                // 4 independent 8B gathers
                uint2 r00 = fb[oy0 + ox0];
                uint2 r01 = fb[oy0 + ox1];
                uint2 r10 = fb[oy1 + ox0];
                uint2 r11 = fb[oy1 + ox1];

                // corner weights: fp32 products, broadcast to half2
                const float wx0 = tx.z, wx1 = tx.w;
                const __half2 w00 = __float2half2_rn(wy0 * wx0);
                const __half2 w01 = __float2half2_rn(wy0 * wx1);
                const __half2 w10 = __float2half2_rn(wy1 * wx0);
                const __half2 w11 = __float2half2_rn(wy1 * wx1);

                const __half2 f00a = *reinterpret_cast<__half2*>(&r00.x);
                const __half2 f00b = *reinterpret_cast<__half2*>(&r00.y);
                const __half2 f01a = *reinterpret_cast<__half2*>(&r01.x);
                const __half2 f01b = *reinterpret_cast<__half2*>(&r01.y);
                const __half2 f10a = *reinterpret_cast<__half2*>(&r10.x);
                const __half2 f10b = *reinterpret_cast<__half2*>(&r10.y);
                const __half2 f11a = *reinterpret_cast<__half2*>(&r11.x);
                const __half2 f11b = *reinterpret_cast<__half2*>(&r11.y);

                __half2 va = __hmul2(f00a, w00);
                __half2 vb = __hmul2(f00b, w00);
                va = __hfma2(f01a, w01, va);
                vb = __hfma2(f01b, w01, vb);
                va = __hfma2(f10a, w10, va);
                vb = __hfma2(f10b, w10, vb);
                va = __hfma2(f11a, w11, va);
                vb = __hfma2(f11b, w11, vb);

                m01 = __hmax2(m01, va);
                m23 = __hmax2(m23, vb);
            }
        }

        // unpack to fp32 stage (pixel-major, conflict-free float4 store)
        float2 lo = __half22float2(m01);
        float2 hi = __half22float2(m23);
        stage4[p * (PADC / 4) + lane] = make_float4(lo.x, lo.y, hi.x, hi.y);
    }
    __syncthreads();

    // ---- coalesced writeback: 6272 floats, idx = t + k*128 walked incrementally
    float* __restrict__ ob = out + (size_t)n * (C_DIM * 49)
                                 + (size_t)blockIdx.y * (128 * 49);
    int c = t / 49;
    int p = t - c * 49;
    #pragma unroll 7
    for (int k = 0; k < 49; k++) {
        ob[t + k * 128] = stage[p * PADC + c];
        p += 30; c += 2;              // advance by 128 = 2*49 + 30
        if (p >= 49) { p -= 49; c += 1; }
    }
}

// -------------------------------------------------------------------------
extern "C" void kernel_launch(void* const* d_in, const int* in_sizes, int n_in,
                              void* d_out, int out_size) {
    const float* bottom = (const float*)d_in[0];
    const float* rois   = (const float*)d_in[1];
    if (n_in >= 2 && in_sizes[0] == NROI * 5) {
        bottom = (const float*)d_in[1];
        rois   = (const float*)d_in[0];
    }
    float* out = (float*)d_out;

    dim3 tgrid((HW_DIM + 31) / 32, C_DIM / 32);
    transpose_kernel<<<tgrid, dim3(32, 8)>>>(bottom);

    dim3 rgrid(NROI, 4);
    roi_pool_kernel<<<rgrid, 128>>>(rois, out);
}

// round 9
// speedup vs baseline: 1.5173x; 1.0692x over previous
#include <cuda_runtime.h>
#include <cuda_fp16.h>
#include <float.h>

#define C_DIM 512
#define H_DIM 50
#define W_DIM 75
#define HW_DIM (H_DIM * W_DIM)
#define NROI 512
#define PRE 14
#define PADH 264   // stage row stride in halves (= 528B, 16B-aligned)

// channels-last fp16 copy of the feature map: [H*W, C]
__device__ __align__(16) __half g_featT[HW_DIM * C_DIM];

// -------------------------------------------------------------------------
// Tiled transpose + fp16 quantize: bottom [C, H*W] -> g_featT [H*W, C]
// Block covers 64 channels x 32 hw; stores half2 (coalesced 128B rows).
// -------------------------------------------------------------------------
__global__ void transpose_kernel(const float* __restrict__ in) {
    __shared__ float tile[64][33];
    int hw0 = blockIdx.x * 32;
    int c0  = blockIdx.y * 64;
    int tx = threadIdx.x, ty = threadIdx.y;

    #pragma unroll
    for (int j = 0; j < 64; j += 8) {
        int hw = hw0 + tx;
        int c  = c0 + ty + j;
        if (hw < HW_DIM) tile[ty + j][tx] = in[c * HW_DIM + hw];
    }
    __syncthreads();
    #pragma unroll
    for (int j = 0; j < 32; j += 8) {
        int hw = hw0 + ty + j;
        if (hw < HW_DIM) {
            __half2 v = __floats2half2_rn(tile[2 * tx][ty + j],
                                          tile[2 * tx + 1][ty + j]);
            *reinterpret_cast<__half2*>(&g_featT[hw * C_DIM + c0 + 2 * tx]) = v;
        }
    }
}

// -------------------------------------------------------------------------
// Main kernel: grid (512 rois, 2 channel-halves), 128 threads (4 warps).
// Lane owns 8 consecutive channels (16B fp16 LDG.128 = 4 half2); warp covers
// a 256-channel half; the 4 warps split the 49 output pixels round-robin.
// Bilinear sample = corner-sum in half2 with fp32-computed corner weights.
// -------------------------------------------------------------------------
__global__ __launch_bounds__(128, 7) void roi_pool_kernel(
    const float* __restrict__ rois, float* __restrict__ out) {

    // Packed corner tables: (.x = off0 bits, .y = off1 bits, .z = w0, .w = w1),
    // offsets in 8-channel (uint4) units.
    __shared__ float4 tabx[PRE], taby[PRE];
    __shared__ __align__(16) __half stage[49 * PADH];

    const int n = blockIdx.x;
    const int t = threadIdx.x;

    // ---- per-ROI corner tables (threads 0..27) ----
    if (t < 2 * PRE) {
        const int axis = (t >= PRE);          // 0 = x, 1 = y
        const int i = axis ? (t - PRE) : t;
        const float lo = rois[n * 5 + (axis ? 2 : 1)] * (1.0f / 16.0f);
        const float hi = rois[n * 5 + (axis ? 4 : 3)] * (1.0f / 16.0f);
        const int D = axis ? H_DIM : W_DIM;

        // replicate reference math exactly
        float s  = (hi - lo) / (float)(D - 1);
        float tt = (lo + hi - (float)(D - 1)) / (float)(D - 1);
        float base = -1.0f + (float)i * (2.0f / 13.0f);
        float g  = s * base + tt;
        float xc = (g + 1.0f) * 0.5f * (float)(D - 1);

        float f0 = floorf(xc);
        int   i0 = (int)f0;
        float w1 = xc - f0;
        float w0 = 1.0f - w1;
        float v0 = (i0 >= 0 && i0 <= D - 1) ? 1.0f : 0.0f;
        float v1 = (i0 + 1 >= 0 && i0 + 1 <= D - 1) ? 1.0f : 0.0f;
        int c0 = min(max(i0, 0), D - 1);
        int c1 = min(max(i0 + 1, 0), D - 1);

        int mul = axis ? (W_DIM * (C_DIM / 8)) : (C_DIM / 8);
        float4 e;
        e.x = __int_as_float(c0 * mul);
        e.y = __int_as_float(c1 * mul);
        e.z = w0 * v0;
        e.w = w1 * v1;
        if (axis) taby[i] = e; else tabx[i] = e;
    }
    __syncthreads();

    const int w    = t >> 5;
    const int lane = t & 31;
    const uint4* __restrict__ fb =
        (const uint4*)g_featT + blockIdx.y * 32 + lane;

    const __half2 HMIN = __float2half2_rn(-60000.0f);

    for (int p = w; p < 49; p += 4) {
        const int py = p / 7;
        const int px = p - py * 7;

        const float4 tx0 = tabx[2 * px];
        const float4 tx1 = tabx[2 * px + 1];
        const float4 ty0 = taby[2 * py];
        const float4 ty1 = taby[2 * py + 1];

        __half2 m0 = HMIN, m1 = HMIN, m2 = HMIN, m3 = HMIN;

        #pragma unroll
        for (int dy = 0; dy < 2; dy++) {
            const float4 ty = dy ? ty1 : ty0;
            const int oy0 = __float_as_int(ty.x);
            const int oy1 = __float_as_int(ty.y);
            const float wy0 = ty.z, wy1 = ty.w;
            #pragma unroll
            for (int dx = 0; dx < 2; dx++) {
                const float4 tx = dx ? tx1 : tx0;
                const int ox0 = __float_as_int(tx.x);
                const int ox1 = __float_as_int(tx.y);

                // 4 independent 16B gathers (8 fp16 channels each)
                uint4 r00 = fb[oy0 + ox0];
                uint4 r01 = fb[oy0 + ox1];
                uint4 r10 = fb[oy1 + ox0];
                uint4 r11 = fb[oy1 + ox1];

                // corner weights: fp32 products, broadcast to half2
                const float wx0 = tx.z, wx1 = tx.w;
                const __half2 w00 = __float2half2_rn(wy0 * wx0);
                const __half2 w01 = __float2half2_rn(wy0 * wx1);
                const __half2 w10 = __float2half2_rn(wy1 * wx0);
                const __half2 w11 = __float2half2_rn(wy1 * wx1);

                const __half2* h00 = reinterpret_cast<const __half2*>(&r00);
                const __half2* h01 = reinterpret_cast<const __half2*>(&r01);
                const __half2* h10 = reinterpret_cast<const __half2*>(&r10);
                const __half2* h11 = reinterpret_cast<const __half2*>(&r11);

                __half2 v0 = __hmul2(h00[0], w00);
                __half2 v1 = __hmul2(h00[1], w00);
                __half2 v2 = __hmul2(h00[2], w00);
                __half2 v3 = __hmul2(h00[3], w00);
                v0 = __hfma2(h01[0], w01, v0);
                v1 = __hfma2(h01[1], w01, v1);
                v2 = __hfma2(h01[2], w01, v2);
                v3 = __hfma2(h01[3], w01, v3);
                v0 = __hfma2(h10[0], w10, v0);
                v1 = __hfma2(h10[1], w10, v1);
                v2 = __hfma2(h10[2], w10, v2);
                v3 = __hfma2(h10[3], w10, v3);
                v0 = __hfma2(h11[0], w11, v0);
                v1 = __hfma2(h11[1], w11, v1);
                v2 = __hfma2(h11[2], w11, v2);
                v3 = __hfma2(h11[3], w11, v3);

                m0 = __hmax2(m0, v0);
                m1 = __hmax2(m1, v1);
                m2 = __hmax2(m2, v2);
                m3 = __hmax2(m3, v3);
            }
        }

        // pixel-major fp16 stage: 16B STS, lane-consecutive -> conflict-free
        uint4 pk;
        pk.x = *reinterpret_cast<unsigned int*>(&m0);
        pk.y = *reinterpret_cast<unsigned int*>(&m1);
        pk.z = *reinterpret_cast<unsigned int*>(&m2);
        pk.w = *reinterpret_cast<unsigned int*>(&m3);
        *reinterpret_cast<uint4*>(&stage[p * PADH + lane * 8]) = pk;
    }
    __syncthreads();

    // ---- coalesced writeback: 256*49 = 12544 floats, idx = t + k*128
    // walked incrementally over (c, p), p fastest.
    float* __restrict__ ob = out + (size_t)n * (C_DIM * 49)
                                 + (size_t)blockIdx.y * (256 * 49);
    int c = t / 49;
    int p = t - c * 49;
    #pragma unroll 7
    for (int k = 0; k < 98; k++) {
        ob[t + k * 128] = __half2float(stage[p * PADH + c]);
        p += 30; c += 2;              // advance by 128 = 2*49 + 30
        if (p >= 49) { p -= 49; c += 1; }
    }
}

// -------------------------------------------------------------------------
extern "C" void kernel_launch(void* const* d_in, const int* in_sizes, int n_in,
                              void* d_out, int out_size) {
    const float* bottom = (const float*)d_in[0];
    const float* rois   = (const float*)d_in[1];
    if (n_in >= 2 && in_sizes[0] == NROI * 5) {
        bottom = (const float*)d_in[1];
        rois   = (const float*)d_in[0];
    }
    float* out = (float*)d_out;

    dim3 tgrid((HW_DIM + 31) / 32, C_DIM / 64);
    transpose_kernel<<<tgrid, dim3(32, 8)>>>(bottom);

    dim3 rgrid(NROI, 2);
    roi_pool_kernel<<<rgrid, 128>>>(rois, out);
}